// round 1
// baseline (speedup 1.0000x reference)
#include <cuda_runtime.h>
#include <cstdint>

#define NTHREADS 512

// Problem constants
#define T_CO 16
#define BATCH 16
#define NH 28
#define NW 28
#define CCH 64
#define KCH 64
#define ROW_FLOATS (NW * CCH)                 // 1792 floats per (t,b,h) tile
#define WEIGHT_T_FLOATS (CCH * KCH)           // 4096
#define TRANS_T_STRIDE (BATCH * NH * NW * CCH) // 802816
#define TRANS_B_STRIDE (NH * NW * CCH)         // 50176

// Shared memory layout (in floats)
// mix  : [16][28][64]                = 28672 floats (112 KB)
// tbuf : 2 buffers x 1792 float2     =  7168 floats ( 28 KB)  trans, value-duplicated
// wbuf : 2 buffers x 4096 floats     =  8192 floats ( 32 KB)
#define MIX_OFF 0
#define TBUF_OFF 28672
#define WBUF_OFF (28672 + 7168)
#define SMEM_FLOATS (WBUF_OFF + 2 * WEIGHT_T_FLOATS)   // 44032
#define SMEM_BYTES (SMEM_FLOATS * 4)                   // 176128

__device__ __forceinline__ void fma2(unsigned long long& d,
                                     unsigned long long a,
                                     unsigned long long b) {
    asm volatile("fma.rn.f32x2 %0, %1, %2, %0;" : "+l"(d) : "l"(a), "l"(b));
}

__device__ __forceinline__ void cp16(uint32_t saddr, const void* g) {
    asm volatile("cp.async.cg.shared.global [%0], [%1], 16;" :: "r"(saddr), "l"(g));
}

__device__ __forceinline__ float2 f2add(float2 a, float2 b) { return make_float2(a.x + b.x, a.y + b.y); }
__device__ __forceinline__ float2 f2sub(float2 a, float2 b) { return make_float2(a.x - b.x, a.y - b.y); }

__global__ void __launch_bounds__(NTHREADS, 1)
iwht2_kernel(const float* __restrict__ tr1, const float* __restrict__ tr2,
             const float* __restrict__ w1,  const float* __restrict__ w2,
             const float* __restrict__ b1,  const float* __restrict__ b2,
             float* __restrict__ out, size_t out_stream_stride)
{
    extern __shared__ float sm[];
    float*  mix  = sm + MIX_OFF;                 // [t*1792 + w*64 + k]
    float2* tbuf = (float2*)(sm + TBUF_OFF);     // [buf*1792 + e], duplicated values
    float*  wbuf = sm + WBUF_OFF;                // [buf*4096 + c*64 + k]

    const int bi  = blockIdx.x;
    const int s   = bi / (BATCH * NH);
    const int rem = bi - s * (BATCH * NH);
    const int b   = rem / NH;
    const int h   = rem - b * NH;

    const float* tr = s ? tr2 : tr1;
    const float* wt = s ? w2  : w1;
    const float* bs = s ? b2  : b1;
    float* outp = out + (size_t)s * out_stream_stride;

    const int tid = threadIdx.x;
    const float* trbase = tr + (size_t)b * TRANS_B_STRIDE + (size_t)h * ROW_FLOATS;

    // ---- prologue: weight[0] via cp.async, trans[0] into regs ----
    {
        const float4* g = (const float4*)wt;   // t=0
        uint32_t sbase = (uint32_t)__cvta_generic_to_shared(wbuf);
        #pragma unroll
        for (int q = 0; q < 2; q++) {
            int idx = q * NTHREADS + tid;      // 1024 x 16B
            cp16(sbase + idx * 16, g + idx);
        }
        asm volatile("cp.async.commit_group;");
    }
    float tv[4];
    {
        const float* g = trbase;               // t=0
        #pragma unroll
        for (int q = 0; q < 4; q++) {
            int e = q * NTHREADS + tid;
            if (e < ROW_FLOATS) tv[q] = __ldg(g + e);
        }
    }

    const int wwarp = tid >> 5;                 // 0..15 -> primary w row
    const int kt    = tid & 31;                 // k-pair index (k = 2*kt)
    const int w0    = wwarp;
    const bool has2 = (wwarp < 12);
    const int w1i   = has2 ? (wwarp + 16) : wwarp;  // dummy alias when !has2 (not stored)

    for (int t = 0; t < T_CO; t++) {
        const int buf = t & 1;
        asm volatile("cp.async.wait_group 0;" ::: "memory");

        // stage duplicated trans values into smem
        #pragma unroll
        for (int q = 0; q < 4; q++) {
            int e = q * NTHREADS + tid;
            if (e < ROW_FLOATS) tbuf[buf * ROW_FLOATS + e] = make_float2(tv[q], tv[q]);
        }
        __syncthreads();

        // prefetch next t while computing
        if (t + 1 < T_CO) {
            const float4* g = (const float4*)(wt + (size_t)(t + 1) * WEIGHT_T_FLOATS);
            uint32_t sbase = (uint32_t)__cvta_generic_to_shared(wbuf + (buf ^ 1) * WEIGHT_T_FLOATS);
            #pragma unroll
            for (int q = 0; q < 2; q++) {
                int idx = q * NTHREADS + tid;
                cp16(sbase + idx * 16, g + idx);
            }
            asm volatile("cp.async.commit_group;");
            const float* g2 = trbase + (size_t)(t + 1) * TRANS_T_STRIDE;
            #pragma unroll
            for (int q = 0; q < 4; q++) {
                int e = q * NTHREADS + tid;
                if (e < ROW_FLOATS) tv[q] = __ldg(g2 + e);
            }
        }

        // ---- GEMM: mixed[t, w, k] = sum_c trans[w,c] * W[c,k], packed f32x2 over k ----
        const ulonglong2* t0p = (const ulonglong2*)(tbuf + buf * ROW_FLOATS + w0  * CCH);
        const ulonglong2* t1p = (const ulonglong2*)(tbuf + buf * ROW_FLOATS + w1i * CCH);
        const unsigned long long* wbp =
            (const unsigned long long*)(wbuf + buf * WEIGHT_T_FLOATS);

        unsigned long long acc0 = 0ULL, acc1 = 0ULL;
        #pragma unroll
        for (int c2 = 0; c2 < 32; c2++) {
            ulonglong2 a0 = t0p[c2];
            ulonglong2 a1 = t1p[c2];
            unsigned long long bb0 = wbp[(2 * c2)     * 32 + kt];
            unsigned long long bb1 = wbp[(2 * c2 + 1) * 32 + kt];
            fma2(acc0, a0.x, bb0);
            fma2(acc1, a1.x, bb0);
            fma2(acc0, a0.y, bb1);
            fma2(acc1, a1.y, bb1);
        }

        float2* mixf2 = (float2*)mix;
        mixf2[t * 896 + w0 * 32 + kt] = *(float2*)&acc0;
        if (has2) mixf2[t * 896 + w1i * 32 + kt] = *(float2*)&acc1;
        // no trailing sync needed: next iter writes the other buffers, mix[t] read after final sync
    }

    __syncthreads();

    // ---- combine: inverse 2D 4-pt WHT over t = 4u+v, scale 1/16, + bias ----
    const float2* mixf2 = (const float2*)mix;
    const float2* bias2 = (const float2*)bs;
    const size_t obase = (size_t)b * (112 * 112 * 64) + (size_t)h * (4 * 112 * 64);

    for (int it = 0; it < 2; it++) {
        int ep = it * NTHREADS + tid;           // 0..895 = w(28) x kpair(32)
        if (ep < 896) {
            int w  = ep >> 5;
            int kp = ep & 31;

            float2 m[16];
            #pragma unroll
            for (int t = 0; t < 16; t++) m[t] = mixf2[t * 896 + w * 32 + kp];

            // stage 1: transform over v (for each u): r[4u+j] = sum_v H4[j,v] m[4u+v]
            float2 r[16];
            #pragma unroll
            for (int u = 0; u < 4; u++) {
                float2 m0 = m[4*u], m1 = m[4*u+1], m2 = m[4*u+2], m3 = m[4*u+3];
                float2 s0 = f2add(m0, m1), d0 = f2sub(m0, m1);
                float2 s1 = f2add(m2, m3), d1 = f2sub(m2, m3);
                r[4*u + 0] = f2add(s0, s1);
                r[4*u + 1] = f2add(d0, d1);
                r[4*u + 2] = f2sub(s0, s1);
                r[4*u + 3] = f2sub(d0, d1);
            }

            float2 bv = bias2[kp];
            float* op = outp + obase + (size_t)w * (4 * 64) + 2 * kp;

            // stage 2: transform over u (for each j): o[i][j] = sum_u H4[i,u] r[4u+j]
            #pragma unroll
            for (int j = 0; j < 4; j++) {
                float2 r0 = r[j], r1 = r[4 + j], r2 = r[8 + j], r3 = r[12 + j];
                float2 s0 = f2add(r0, r1), d0 = f2sub(r0, r1);
                float2 s1 = f2add(r2, r3), d1 = f2sub(r2, r3);
                float2 o0 = f2add(s0, s1);
                float2 o1 = f2add(d0, d1);
                float2 o2 = f2sub(s0, s1);
                float2 o3 = f2sub(d0, d1);
                float2 v0 = make_float2(fmaf(o0.x, 0.0625f, bv.x), fmaf(o0.y, 0.0625f, bv.y));
                float2 v1 = make_float2(fmaf(o1.x, 0.0625f, bv.x), fmaf(o1.y, 0.0625f, bv.y));
                float2 v2 = make_float2(fmaf(o2.x, 0.0625f, bv.x), fmaf(o2.y, 0.0625f, bv.y));
                float2 v3 = make_float2(fmaf(o3.x, 0.0625f, bv.x), fmaf(o3.y, 0.0625f, bv.y));
                *reinterpret_cast<float2*>(op + 0 * 7168 + j * 64) = v0;
                *reinterpret_cast<float2*>(op + 1 * 7168 + j * 64) = v1;
                *reinterpret_cast<float2*>(op + 2 * 7168 + j * 64) = v2;
                *reinterpret_cast<float2*>(op + 3 * 7168 + j * 64) = v3;
            }
        }
    }
}

extern "C" void kernel_launch(void* const* d_in, const int* in_sizes, int n_in,
                              void* d_out, int out_size) {
    (void)in_sizes; (void)n_in;
    const float* tr1 = (const float*)d_in[0];
    const float* tr2 = (const float*)d_in[1];
    const float* w1  = (const float*)d_in[2];
    const float* w2  = (const float*)d_in[3];
    const float* b1  = (const float*)d_in[4];
    const float* b2  = (const float*)d_in[5];
    float* out = (float*)d_out;

    cudaFuncSetAttribute(iwht2_kernel,
                         cudaFuncAttributeMaxDynamicSharedMemorySize, SMEM_BYTES);

    size_t stream_stride = (size_t)out_size / 2;   // out1 then out2
    iwht2_kernel<<<2 * BATCH * NH, NTHREADS, SMEM_BYTES>>>(
        tr1, tr2, w1, w2, b1, b2, out, stream_stride);
}

// round 2
// speedup vs baseline: 2.1376x; 2.1376x over previous
#include <cuda_runtime.h>
#include <cstdint>

#define NTHREADS 512

// Problem constants
#define T_CO 16
#define BATCH 16
#define NH 28
#define NW 28
#define CCH 64
#define KCH 64
#define ROW_FLOATS (NW * CCH)                  // 1792 floats per (t,b,h) tile
#define WEIGHT_T_FLOATS (CCH * KCH)            // 4096
#define TRANS_T_STRIDE (BATCH * NH * NW * CCH) // 802816
#define TRANS_B_STRIDE (NH * NW * CCH)         // 50176

// Shared memory (floats):
// mix : [16][28][64]  = 28672 floats (112 KB)   mixed coefficients
// trs : [16][28][64]  = 28672 floats (112 KB)   trans, XOR-swizzled float4 rows
#define MIX_OFF 0
#define TRS_OFF 28672
#define SMEM_FLOATS (TRS_OFF + 28672)
#define SMEM_BYTES (SMEM_FLOATS * 4)           // 229376

__device__ __forceinline__ void fma2(unsigned long long& d,
                                     unsigned long long a,
                                     unsigned long long b) {
    asm volatile("fma.rn.f32x2 %0, %1, %2, %0;" : "+l"(d) : "l"(a), "l"(b));
}

__device__ __forceinline__ unsigned long long dup2(float x) {
    unsigned long long r;
    asm("mov.b64 %0, {%1, %1};" : "=l"(r) : "f"(x));
    return r;
}

__device__ __forceinline__ void cp16(uint32_t saddr, const void* g) {
    asm volatile("cp.async.cg.shared.global [%0], [%1], 16;" :: "r"(saddr), "l"(g));
}

__device__ __forceinline__ float2 f2add(float2 a, float2 b) { return make_float2(a.x + b.x, a.y + b.y); }
__device__ __forceinline__ float2 f2sub(float2 a, float2 b) { return make_float2(a.x - b.x, a.y - b.y); }

__global__ void __launch_bounds__(NTHREADS, 1)
iwht2_kernel(const float* __restrict__ tr1, const float* __restrict__ tr2,
             const float* __restrict__ w1,  const float* __restrict__ w2,
             const float* __restrict__ b1,  const float* __restrict__ b2,
             float* __restrict__ out, size_t out_stream_stride)
{
    extern __shared__ float sm[];
    float* mix = sm + MIX_OFF;   // [t][w][k] as float; accessed as float2 [t*896 + w*32 + kp]
    float* trs = sm + TRS_OFF;   // [t][row][c], float4 segments swizzled: seg' = seg ^ (row&3)

    const int bi  = blockIdx.x;
    const int s   = bi / (BATCH * NH);
    const int rem = bi - s * (BATCH * NH);
    const int b   = rem / NH;
    const int h   = rem - b * NH;

    const float* tr = s ? tr2 : tr1;
    const float* wt = s ? w2  : w1;
    const float* bs = s ? b2  : b1;
    float* outp = out + (size_t)s * out_stream_stride;

    const int tid = threadIdx.x;
    const float* trbase = tr + (size_t)b * TRANS_B_STRIDE + (size_t)h * ROW_FLOATS;

    // ---- stage all 16 coefficient tiles of trans into swizzled smem ----
    // 16 t x 448 float4 = 7168 float4 loads, 14 per thread
    #pragma unroll
    for (int q = 0; q < 14; q++) {
        int idx = q * NTHREADS + tid;
        int t   = idx / 448;
        int e   = idx - t * 448;            // float4 index within (t) tile
        int row = e >> 4;
        int c4  = e & 15;
        const float4* g = (const float4*)(trbase + (size_t)t * TRANS_T_STRIDE) + e;
        float* dst = trs + t * ROW_FLOATS + row * 64 + ((c4 ^ (row & 3)) << 2);
        cp16((uint32_t)__cvta_generic_to_shared(dst), g);
    }
    asm volatile("cp.async.commit_group;");
    asm volatile("cp.async.wait_group 0;" ::: "memory");
    __syncthreads();

    // ---- GEMM: warp tw handles coefficient t = tw ----
    // lane = rg*8 + kg : rows rg*7 .. rg*7+6, k-floats [8*kg, 8*kg+8)
    {
        const int t    = tid >> 5;
        const int lane = tid & 31;
        const int rg   = lane >> 3;
        const int kg   = lane & 7;

        const float* trs_t = trs + t * ROW_FLOATS;
        const ulonglong2* wp = (const ulonglong2*)(wt + (size_t)t * WEIGHT_T_FLOATS) + kg * 2;

        unsigned long long acc[7][4];
        #pragma unroll
        for (int r = 0; r < 7; r++)
            #pragma unroll
            for (int j = 0; j < 4; j++) acc[r][j] = 0ULL;

        #pragma unroll 4
        for (int c4 = 0; c4 < 16; c4++) {
            float4 tv[7];
            #pragma unroll
            for (int r = 0; r < 7; r++) {
                int row = rg * 7 + r;
                tv[r] = *(const float4*)(trs_t + row * 64 + ((c4 ^ (row & 3)) << 2));
            }
            #pragma unroll
            for (int cc = 0; cc < 4; cc++) {
                int c = c4 * 4 + cc;
                ulonglong2 wv0 = wp[c * 16];
                ulonglong2 wv1 = wp[c * 16 + 1];
                #pragma unroll
                for (int r = 0; r < 7; r++) {
                    float x = (cc == 0) ? tv[r].x : (cc == 1) ? tv[r].y
                            : (cc == 2) ? tv[r].z : tv[r].w;
                    unsigned long long a = dup2(x);
                    fma2(acc[r][0], a, wv0.x);
                    fma2(acc[r][1], a, wv0.y);
                    fma2(acc[r][2], a, wv1.x);
                    fma2(acc[r][3], a, wv1.y);
                }
            }
        }

        // store to mix: [t*896 + row*32 + kpair] (float2 units)
        float2* mixf2 = (float2*)mix;
        #pragma unroll
        for (int r = 0; r < 7; r++) {
            int row = rg * 7 + r;
            ulonglong2* dst = (ulonglong2*)(mixf2 + t * 896 + row * 32 + kg * 4);
            dst[0] = make_ulonglong2(acc[r][0], acc[r][1]);
            dst[1] = make_ulonglong2(acc[r][2], acc[r][3]);
        }
    }

    __syncthreads();

    // ---- combine: inverse 2D 4-pt WHT over t = 4u+v, scale 1/16, + bias ----
    const float2* mixf2 = (const float2*)mix;
    const float2* bias2 = (const float2*)bs;
    const size_t obase = (size_t)b * (112 * 112 * 64) + (size_t)h * (4 * 112 * 64);

    #pragma unroll
    for (int it = 0; it < 2; it++) {
        int ep = it * NTHREADS + tid;           // 0..895 = w(28) x kpair(32)
        if (ep < 896) {
            int w  = ep >> 5;
            int kp = ep & 31;

            float2 m[16];
            #pragma unroll
            for (int t = 0; t < 16; t++) m[t] = mixf2[t * 896 + w * 32 + kp];

            // stage 1: transform over v (for each u)
            float2 r[16];
            #pragma unroll
            for (int u = 0; u < 4; u++) {
                float2 m0 = m[4*u], m1 = m[4*u+1], m2 = m[4*u+2], m3 = m[4*u+3];
                float2 s0 = f2add(m0, m1), d0 = f2sub(m0, m1);
                float2 s1 = f2add(m2, m3), d1 = f2sub(m2, m3);
                r[4*u + 0] = f2add(s0, s1);
                r[4*u + 1] = f2add(d0, d1);
                r[4*u + 2] = f2sub(s0, s1);
                r[4*u + 3] = f2sub(d0, d1);
            }

            float2 bv = bias2[kp];
            float* op = outp + obase + (size_t)w * (4 * 64) + 2 * kp;

            // stage 2: transform over u (for each j)
            #pragma unroll
            for (int j = 0; j < 4; j++) {
                float2 r0 = r[j], r1 = r[4 + j], r2 = r[8 + j], r3 = r[12 + j];
                float2 s0 = f2add(r0, r1), d0 = f2sub(r0, r1);
                float2 s1 = f2add(r2, r3), d1 = f2sub(r2, r3);
                float2 o0 = f2add(s0, s1);
                float2 o1 = f2add(d0, d1);
                float2 o2 = f2sub(s0, s1);
                float2 o3 = f2sub(d0, d1);
                float2 v0 = make_float2(fmaf(o0.x, 0.0625f, bv.x), fmaf(o0.y, 0.0625f, bv.y));
                float2 v1 = make_float2(fmaf(o1.x, 0.0625f, bv.x), fmaf(o1.y, 0.0625f, bv.y));
                float2 v2 = make_float2(fmaf(o2.x, 0.0625f, bv.x), fmaf(o2.y, 0.0625f, bv.y));
                float2 v3 = make_float2(fmaf(o3.x, 0.0625f, bv.x), fmaf(o3.y, 0.0625f, bv.y));
                *reinterpret_cast<float2*>(op + 0 * 7168 + j * 64) = v0;
                *reinterpret_cast<float2*>(op + 1 * 7168 + j * 64) = v1;
                *reinterpret_cast<float2*>(op + 2 * 7168 + j * 64) = v2;
                *reinterpret_cast<float2*>(op + 3 * 7168 + j * 64) = v3;
            }
        }
    }
}

extern "C" void kernel_launch(void* const* d_in, const int* in_sizes, int n_in,
                              void* d_out, int out_size) {
    (void)in_sizes; (void)n_in;
    const float* tr1 = (const float*)d_in[0];
    const float* tr2 = (const float*)d_in[1];
    const float* w1  = (const float*)d_in[2];
    const float* w2  = (const float*)d_in[3];
    const float* b1  = (const float*)d_in[4];
    const float* b2  = (const float*)d_in[5];
    float* out = (float*)d_out;

    cudaFuncSetAttribute(iwht2_kernel,
                         cudaFuncAttributeMaxDynamicSharedMemorySize, SMEM_BYTES);

    size_t stream_stride = (size_t)out_size / 2;   // out1 then out2
    iwht2_kernel<<<2 * BATCH * NH, NTHREADS, SMEM_BYTES>>>(
        tr1, tr2, w1, w2, b1, b2, out, stream_stride);
}